// round 13
// baseline (speedup 1.0000x reference)
#include <cuda_runtime.h>
#include <cuda_fp16.h>
#include <cstdint>
#include <math.h>

// Problem constants
#define E_DIM   1024
#define N_HEADS 16
#define H_DIM   64
#define BATCH   4
#define SQ      1024
#define SKV     2048
#define MQ      (BATCH * SQ)    // 4096
#define MKV     (BATCH * SKV)   // 8192

// ---------------------------------------------------------------------------
// Persistent planes (device globals). All single fp16 planes.
// ---------------------------------------------------------------------------
__device__ __align__(16) uint16_t g_x1h[MQ * E_DIM];
__device__ __align__(16) uint16_t g_x2h[MKV * E_DIM];
__device__ __align__(16) uint16_t g_wqh[E_DIM * E_DIM];
__device__ __align__(16) uint16_t g_wkh[E_DIM * E_DIM];
__device__ __align__(16) uint16_t g_wvh[E_DIM * E_DIM];
__device__ __align__(16) uint16_t g_woh[E_DIM * E_DIM];
__device__ __align__(16) uint16_t g_qh[MQ * E_DIM];
__device__ __align__(16) uint16_t g_kh[MKV * E_DIM];
__device__ __align__(16) uint16_t g_vh[MKV * E_DIM];
__device__ __align__(16) uint16_t g_ah[MQ * E_DIM];

// ---------------------------------------------------------------------------
// Helpers
// ---------------------------------------------------------------------------
#define SMEM_SWIZZLE_128B(off) ((off) ^ (((off) >> 3) & 0x70))
#define SMEM_SWIZZLE_64B(off)  ((off) ^ (((off) >> 3) & 0x30))

#define LDSM_X4(r0_,r1_,r2_,r3_,addr_) \
    asm volatile("ldmatrix.sync.aligned.m8n8.x4.shared.b16 {%0,%1,%2,%3}, [%4];" \
        : "=r"(r0_), "=r"(r1_), "=r"(r2_), "=r"(r3_) : "r"(addr_))

#define LDSM_X4_T(r0_,r1_,r2_,r3_,addr_) \
    asm volatile("ldmatrix.sync.aligned.m8n8.x4.trans.shared.b16 {%0,%1,%2,%3}, [%4];" \
        : "=r"(r0_), "=r"(r1_), "=r"(r2_), "=r"(r3_) : "r"(addr_))

#define MMAF16(d_,a_,b_) \
    asm volatile("mma.sync.aligned.m16n8k16.row.col.f32.f16.f16.f32 " \
        "{%0,%1,%2,%3}, {%4,%5,%6,%7}, {%8,%9}, {%0,%1,%2,%3};" \
        : "+f"((d_)[0]), "+f"((d_)[1]), "+f"((d_)[2]), "+f"((d_)[3]) \
        : "r"((a_)[0]), "r"((a_)[1]), "r"((a_)[2]), "r"((a_)[3]), \
          "r"((b_)[0]), "r"((b_)[1]))

#define CP_ASYNC16(dst_, src_) \
    asm volatile("cp.async.cg.shared.global [%0], [%1], 16;" \
        :: "r"(dst_), "l"(src_))
#define CP_COMMIT() asm volatile("cp.async.commit_group;" ::: "memory")
#define CP_WAIT2()  asm volatile("cp.async.wait_group 2;" ::: "memory")
#define CP_WAIT1()  asm volatile("cp.async.wait_group 1;" ::: "memory")
#define CP_WAIT0()  asm volatile("cp.async.wait_group 0;" ::: "memory")

__device__ __forceinline__ uint32_t packh2(float x, float y) {
    __half2 t = __floats2half2_rn(x, y);
    return *(uint32_t*)&t;
}

// ---------------------------------------------------------------------------
// ALL fp32 -> single fp16 plane conversions in ONE launch. grid.y = tensor.
// ---------------------------------------------------------------------------
__global__ void __launch_bounds__(256) cvt_all(
    const float* __restrict__ x1, const float* __restrict__ x2,
    const float* __restrict__ w0, const float* __restrict__ w1,
    const float* __restrict__ w2, const float* __restrict__ w3,
    uint16_t* __restrict__ x1h, uint16_t* __restrict__ x2h,
    uint16_t* __restrict__ h0, uint16_t* __restrict__ h1,
    uint16_t* __restrict__ h2, uint16_t* __restrict__ h3)
{
    const int m = blockIdx.y;
    const int idx = blockIdx.x * 256 + threadIdx.x;
    const float* in; uint16_t* hi; int n8;
    switch (m) {
        case 0: in = x1; hi = x1h; n8 = MQ  * E_DIM / 8; break;
        case 1: in = x2; hi = x2h; n8 = MKV * E_DIM / 8; break;
        case 2: in = w0; hi = h0;  n8 = E_DIM * E_DIM / 8; break;
        case 3: in = w1; hi = h1;  n8 = E_DIM * E_DIM / 8; break;
        case 4: in = w2; hi = h2;  n8 = E_DIM * E_DIM / 8; break;
        default:in = w3; hi = h3;  n8 = E_DIM * E_DIM / 8; break;
    }
    if (idx >= n8) return;
    const float4 f0 = ((const float4*)in)[2 * idx];
    const float4 f1 = ((const float4*)in)[2 * idx + 1];
    uint4 h;
    h.x = packh2(f0.x, f0.y); h.y = packh2(f0.z, f0.w);
    h.z = packh2(f1.x, f1.y); h.w = packh2(f1.z, f1.w);
    ((uint4*)hi)[idx] = h;
}

// ---------------------------------------------------------------------------
// fp16 HMMA GEMM body (single-B): C = A @ B^T (+bias)(*scale), 1 MMA/k-step.
// 6-stage cp.async ring (16KB/stage = 96KB, 2 CTAs/SM), 2 chunks consumed per
// __syncthreads (16 barriers instead of 32).
// wmode: 0 = fp32 out, 3 = fp16 single plane
// ---------------------------------------------------------------------------
#define GS_A    0
#define GS_B    8192
#define G_STAGE 16384
#define G_SMEM  98304       // 6 stages
#define G_NCHUNK 32

template<int WMODE>
__device__ __forceinline__ void gemm_body(
    const uint16_t* __restrict__ Ah, const uint16_t* __restrict__ Bh,
    const float* __restrict__ bias, float scale,
    float* __restrict__ Cf, uint16_t* __restrict__ Ch,
    char* smem, const int m0, const int n0)
{
    const uint32_t sb = (uint32_t)__cvta_generic_to_shared(smem);
    const int tid  = threadIdx.x;
    const int wid  = tid >> 5;
    const int lane = tid & 31;

    const int warp_m = (wid & 1) * 64;
    const int warp_n = (wid >> 1) * 32;
    const int g = lane >> 3;
    const int r = lane & 7;

    float acc[4][4][4];
#pragma unroll
    for (int mi = 0; mi < 4; mi++)
#pragma unroll
        for (int ni = 0; ni < 4; ni++)
#pragma unroll
            for (int q = 0; q < 4; q++) acc[mi][ni][q] = 0.f;

    const int a_row = warp_m + (g & 1) * 8 + r;
    const int a_kc  = (g >> 1) * 8;
    const int b_row = warp_n + (g >> 1) * 8 + r;
    const int b_kc  = (g & 1) * 8;

    auto load_stage = [&](int stage, int ch) {
        const uint32_t sbase = sb + stage * G_STAGE;
#pragma unroll
        for (int it = 0; it < 2; it++) {
            const int idx = it * 256 + tid;     // 0..511
            const int row = idx >> 2;           // 0..127
            const int seg = idx & 3;            // 16B segment
            const uint32_t sw = SMEM_SWIZZLE_64B((uint32_t)(row * 64 + seg * 16));
            const size_t ga = (size_t)(m0 + row) * E_DIM + ch * 32 + seg * 8;
            const size_t gb = (size_t)(n0 + row) * E_DIM + ch * 32 + seg * 8;
            CP_ASYNC16(sbase + GS_A + sw, (const char*)(Ah + ga));
            CP_ASYNC16(sbase + GS_B + sw, (const char*)(Bh + gb));
        }
    };

    // prologue: 4 chunks in flight (one commit group per chunk)
    load_stage(0, 0); CP_COMMIT();
    load_stage(1, 1); CP_COMMIT();
    load_stage(2, 2); CP_COMMIT();
    load_stage(3, 3); CP_COMMIT();

    // consume one chunk from stage st
    auto consume = [&](int st) {
        const uint32_t sbase = sb + st * G_STAGE;
#pragma unroll
        for (int ks = 0; ks < 2; ks++) {
            uint32_t ah[4][4];
#pragma unroll
            for (int mi = 0; mi < 4; mi++) {
                const uint32_t sw = SMEM_SWIZZLE_64B(
                    (uint32_t)((a_row + mi * 16) * 64 + (a_kc + ks * 16) * 2));
                LDSM_X4(ah[mi][0], ah[mi][1], ah[mi][2], ah[mi][3], sbase + GS_A + sw);
            }
            uint32_t bh[4][2];
#pragma unroll
            for (int np = 0; np < 2; np++) {
                const uint32_t sw = SMEM_SWIZZLE_64B(
                    (uint32_t)((b_row + np * 16) * 64 + (b_kc + ks * 16) * 2));
                LDSM_X4(bh[2*np][0], bh[2*np][1], bh[2*np+1][0], bh[2*np+1][1],
                        sbase + GS_B + sw);
            }
#pragma unroll
            for (int mi = 0; mi < 4; mi++)
#pragma unroll
                for (int ni = 0; ni < 4; ni++)
                    MMAF16(acc[mi][ni], ah[mi], bh[ni]);
        }
    };

    for (int i = 0; i < G_NCHUNK / 2; i++) {          // 16 iterations
        const int ch0 = 2 * i;
        if (i < G_NCHUNK / 2 - 1) CP_WAIT2(); else CP_WAIT0();
        __syncthreads();
        // refill: chunks ch0+4, ch0+5 into the stages consumed last iteration
        if (ch0 + 4 < G_NCHUNK) { load_stage((ch0 + 4) % 6, ch0 + 4); CP_COMMIT(); }
        if (ch0 + 5 < G_NCHUNK) { load_stage((ch0 + 5) % 6, ch0 + 5); CP_COMMIT(); }
        consume(ch0 % 6);
        consume((ch0 + 1) % 6);
    }

    // ---- epilogue
    const int erow = lane >> 2;
    const int ecol = (lane & 3) * 2;
#pragma unroll
    for (int ni = 0; ni < 4; ni++) {
        const int col = n0 + warp_n + ni * 8 + ecol;
        const float bv0 = __ldg(bias + col);
        const float bv1 = __ldg(bias + col + 1);
#pragma unroll
        for (int mi = 0; mi < 4; mi++) {
            const int row = m0 + warp_m + mi * 16 + erow;
            float v00 = (acc[mi][ni][0] + bv0) * scale;
            float v01 = (acc[mi][ni][1] + bv1) * scale;
            float v10 = (acc[mi][ni][2] + bv0) * scale;
            float v11 = (acc[mi][ni][3] + bv1) * scale;
            if (WMODE == 3) {
                *(uint32_t*)(Ch + (size_t)row * E_DIM + col)       = packh2(v00, v01);
                *(uint32_t*)(Ch + (size_t)(row + 8) * E_DIM + col) = packh2(v10, v11);
            } else {
                float2 a = {v00, v01}, b = {v10, v11};
                *(float2*)(Cf + (size_t)row * E_DIM + col)       = a;
                *(float2*)(Cf + (size_t)(row + 8) * E_DIM + col) = b;
            }
        }
    }
}

// ---- fused Q/K/V projections: grid (8, 64, 3); z=0 uses only y<32
__global__ void __launch_bounds__(256, 2) gemm_qkv(
    const uint16_t* __restrict__ x1h, const uint16_t* __restrict__ x2h,
    const uint16_t* __restrict__ wqh, const uint16_t* __restrict__ wkh,
    const uint16_t* __restrict__ wvh,
    const float* __restrict__ bq, const float* __restrict__ bk,
    const float* __restrict__ bv,
    uint16_t* __restrict__ qh, uint16_t* __restrict__ kh,
    uint16_t* __restrict__ vh)
{
    extern __shared__ char smem[];
    const int z = blockIdx.z;
    if (z == 0 && blockIdx.y >= MQ / 128) return;
    if (z == 0) {
        gemm_body<3>(x1h, wqh, bq, 0.125f, nullptr, qh,
                     smem, blockIdx.y * 128, blockIdx.x * 128);
    } else if (z == 1) {
        gemm_body<3>(x2h, wkh, bk, 1.0f, nullptr, kh,
                     smem, blockIdx.y * 128, blockIdx.x * 128);
    } else {
        gemm_body<3>(x2h, wvh, bv, 1.0f, nullptr, vh,
                     smem, blockIdx.y * 128, blockIdx.x * 128);
    }
}

// ---- output projection (fp32 out)
__global__ void __launch_bounds__(256, 2) gemm_out(
    const uint16_t* __restrict__ Ah, const uint16_t* __restrict__ Bh,
    const float* __restrict__ bias, float* __restrict__ Cf)
{
    extern __shared__ char smem[];
    gemm_body<0>(Ah, Bh, bias, 1.0f, Cf, nullptr,
                 smem, blockIdx.y * 128, blockIdx.x * 128);
}

// ---------------------------------------------------------------------------
// Flash attention v2 on fp16 HMMA. All operands single fp16 planes:
//   S = Q*K (1 MMA); PV = P*V (1 MMA). fp32 acc + softmax.
// CTA = (b, h, 128 q rows); 8 warps x 16 q rows. KV chunk 64, double-buffered.
// ---------------------------------------------------------------------------
#define AS_Q    0          // 128 rows x 128B = 16KB
#define AS_KV   16384      // stage base
#define AS_K    0
#define AS_V    8192
#define A_STAGE 16384
#define ATT_SMEM 49152     // 16KB Q + 2 x 16KB KV
#define NEG_BIG (-3.0e38f)

__global__ void __launch_bounds__(256, 2) attn_mma(
    const uint16_t* __restrict__ Qh,
    const uint16_t* __restrict__ Kh,
    const uint16_t* __restrict__ Vh,
    uint16_t* __restrict__ Oh)
{
    extern __shared__ char smem[];
    const uint32_t sb = (uint32_t)__cvta_generic_to_shared(smem);
    const int b  = blockIdx.z;
    const int h  = blockIdx.y;
    const int q0 = blockIdx.x * 128;
    const int tid  = threadIdx.x;
    const int wid  = tid >> 5;
    const int lane = tid & 31;
    const int g = lane >> 3;
    const int r = lane & 7;

    // ---- Q tile 128x64 via cp.async
#pragma unroll
    for (int it = 0; it < 4; it++) {
        const int idx = it * 256 + tid;
        const int row = idx >> 3;
        const int seg = idx & 7;
        const uint32_t sw = SMEM_SWIZZLE_128B((uint32_t)(row * 128 + seg * 16));
        const size_t gq = (size_t)(b * SQ + q0 + row) * E_DIM + h * H_DIM + seg * 8;
        CP_ASYNC16(sb + AS_Q + sw, (const char*)(Qh + gq));
    }
    CP_COMMIT();

    auto load_kv = [&](int stage, int c) {
        const uint32_t sbase = sb + AS_KV + stage * A_STAGE;
#pragma unroll
        for (int it = 0; it < 2; it++) {
            const int idx = it * 256 + tid;
            const int row = idx >> 3;
            const int seg = idx & 7;
            const uint32_t sw = SMEM_SWIZZLE_128B((uint32_t)(row * 128 + seg * 16));
            const size_t gk = (size_t)(b * SKV + c + row) * E_DIM + h * H_DIM + seg * 8;
            CP_ASYNC16(sbase + AS_K + sw, (const char*)(Kh + gk));
            CP_ASYNC16(sbase + AS_V + sw, (const char*)(Vh + gk));
        }
    };

    load_kv(0, 0);
    CP_COMMIT();
    CP_WAIT1();          // Q ready
    __syncthreads();

    // ---- persistent Q fragments
    const int a_row = wid * 16 + (g & 1) * 8 + r;
    const int a_kc  = (g >> 1) * 8;
    uint32_t qf[4][4];
#pragma unroll
    for (int ks = 0; ks < 4; ks++) {
        const uint32_t sw = SMEM_SWIZZLE_128B((uint32_t)(a_row * 128 + (a_kc + ks * 16) * 2));
        LDSM_X4(qf[ks][0], qf[ks][1], qf[ks][2], qf[ks][3], sb + AS_Q + sw);
    }

    float o[8][4];
#pragma unroll
    for (int na = 0; na < 8; na++)
#pragma unroll
        for (int q = 0; q < 4; q++) o[na][q] = 0.f;
    float mr0 = NEG_BIG, mr1 = NEG_BIG, lr0 = 0.f, lr1 = 0.f;

    const int kb_row = (g >> 1) * 8 + r;
    const int kb_kc  = (g & 1) * 8;

    const int NCH = SKV / 64;   // 32
    for (int cc = 0; cc < NCH; cc++) {
        const int buf = cc & 1;
        if (cc + 1 < NCH) { load_kv(buf ^ 1, (cc + 1) * 64); CP_COMMIT(); CP_WAIT1(); }
        else              { CP_WAIT0(); }
        __syncthreads();
        const uint32_t kvb = sb + AS_KV + buf * A_STAGE;

        // ---- S = Q K^T (fp16 x1)
        float s[8][4];
#pragma unroll
        for (int na = 0; na < 8; na++)
#pragma unroll
            for (int q = 0; q < 4; q++) s[na][q] = 0.f;

#pragma unroll
        for (int ks = 0; ks < 4; ks++) {
            uint32_t kf[8][2];
#pragma unroll
            for (int np = 0; np < 4; np++) {
                const uint32_t sw = SMEM_SWIZZLE_128B(
                    (uint32_t)((np * 16 + kb_row) * 128 + (kb_kc + ks * 16) * 2));
                LDSM_X4(kf[2*np][0], kf[2*np][1], kf[2*np+1][0], kf[2*np+1][1],
                        kvb + AS_K + sw);
            }
#pragma unroll
            for (int na = 0; na < 8; na++) {
                MMAF16(s[na], qf[ks], kf[na]);
            }
        }

        // ---- online softmax
        float mx0 = NEG_BIG, mx1 = NEG_BIG;
#pragma unroll
        for (int na = 0; na < 8; na++) {
            mx0 = fmaxf(mx0, fmaxf(s[na][0], s[na][1]));
            mx1 = fmaxf(mx1, fmaxf(s[na][2], s[na][3]));
        }
        mx0 = fmaxf(mx0, __shfl_xor_sync(0xffffffffu, mx0, 1));
        mx0 = fmaxf(mx0, __shfl_xor_sync(0xffffffffu, mx0, 2));
        mx1 = fmaxf(mx1, __shfl_xor_sync(0xffffffffu, mx1, 1));
        mx1 = fmaxf(mx1, __shfl_xor_sync(0xffffffffu, mx1, 2));
        const float mn0 = fmaxf(mr0, mx0);
        const float mn1 = fmaxf(mr1, mx1);
        const float al0 = __expf(mr0 - mn0);
        const float al1 = __expf(mr1 - mn1);
        mr0 = mn0; mr1 = mn1;
        float ls0 = 0.f, ls1 = 0.f;
#pragma unroll
        for (int na = 0; na < 8; na++) {
            s[na][0] = __expf(s[na][0] - mn0);
            s[na][1] = __expf(s[na][1] - mn0);
            s[na][2] = __expf(s[na][2] - mn1);
            s[na][3] = __expf(s[na][3] - mn1);
            ls0 += s[na][0] + s[na][1];
            ls1 += s[na][2] + s[na][3];
        }
        ls0 += __shfl_xor_sync(0xffffffffu, ls0, 1);
        ls0 += __shfl_xor_sync(0xffffffffu, ls0, 2);
        ls1 += __shfl_xor_sync(0xffffffffu, ls1, 1);
        ls1 += __shfl_xor_sync(0xffffffffu, ls1, 2);
        lr0 = lr0 * al0 + ls0;
        lr1 = lr1 * al1 + ls1;
#pragma unroll
        for (int na = 0; na < 8; na++) {
            o[na][0] *= al0; o[na][1] *= al0;
            o[na][2] *= al1; o[na][3] *= al1;
        }

        // ---- P @ V (fp16 x1)
#pragma unroll
        for (int kt = 0; kt < 4; kt++) {
            uint32_t ph[4];
            ph[0] = packh2(s[2*kt][0],   s[2*kt][1]);
            ph[1] = packh2(s[2*kt][2],   s[2*kt][3]);
            ph[2] = packh2(s[2*kt+1][0], s[2*kt+1][1]);
            ph[3] = packh2(s[2*kt+1][2], s[2*kt+1][3]);

            uint32_t vf[8][2];
#pragma unroll
            for (int dp = 0; dp < 4; dp++) {
                const uint32_t byte = (uint32_t)((kt * 16 + (lane & 15)) * 128
                                                 + dp * 32 + (lane >> 4) * 16);
                const uint32_t sw = SMEM_SWIZZLE_128B(byte);
                LDSM_X4_T(vf[2*dp][0], vf[2*dp][1], vf[2*dp+1][0], vf[2*dp+1][1],
                          kvb + AS_V + sw);
            }
#pragma unroll
            for (int na = 0; na < 8; na++) {
                MMAF16(o[na], ph, vf[na]);
            }
        }
        __syncthreads();
    }

    // ---- epilogue: normalize, write single fp16 plane
    const float inv0 = 1.f / lr0;
    const float inv1 = 1.f / lr1;
    const int row0 = q0 + wid * 16 + (lane >> 2);
#pragma unroll
    for (int na = 0; na < 8; na++) {
        const int col = h * H_DIM + na * 8 + (lane & 3) * 2;
        const size_t i0 = (size_t)(b * SQ + row0) * E_DIM + col;
        const size_t i1 = (size_t)(b * SQ + row0 + 8) * E_DIM + col;
        *(uint32_t*)(Oh + i0) = packh2(o[na][0] * inv0, o[na][1] * inv0);
        *(uint32_t*)(Oh + i1) = packh2(o[na][2] * inv1, o[na][3] * inv1);
    }
}

// ---------------------------------------------------------------------------
extern "C" void kernel_launch(void* const* d_in, const int* in_sizes, int n_in,
                              void* d_out, int out_size)
{
    const float* x1 = (const float*)d_in[0];
    const float* x2 = (const float*)d_in[1];
    const float* Wq = (const float*)d_in[2];
    const float* bq = (const float*)d_in[3];
    const float* Wk = (const float*)d_in[4];
    const float* bk = (const float*)d_in[5];
    const float* Wv = (const float*)d_in[6];
    const float* bv = (const float*)d_in[7];
    const float* Wo = (const float*)d_in[8];
    const float* bo = (const float*)d_in[9];
    float* out = (float*)d_out;

    uint16_t *x1h, *x2h;
    uint16_t *wqh, *wkh, *wvh, *woh;
    uint16_t *qh, *kh, *vh, *ah;
    cudaGetSymbolAddress((void**)&x1h, g_x1h);
    cudaGetSymbolAddress((void**)&x2h, g_x2h);
    cudaGetSymbolAddress((void**)&wqh, g_wqh);
    cudaGetSymbolAddress((void**)&wkh, g_wkh);
    cudaGetSymbolAddress((void**)&wvh, g_wvh);
    cudaGetSymbolAddress((void**)&woh, g_woh);
    cudaGetSymbolAddress((void**)&qh,  g_qh);
    cudaGetSymbolAddress((void**)&kh,  g_kh);
    cudaGetSymbolAddress((void**)&vh,  g_vh);
    cudaGetSymbolAddress((void**)&ah,  g_ah);

    cudaFuncSetAttribute(gemm_qkv, cudaFuncAttributeMaxDynamicSharedMemorySize, G_SMEM);
    cudaFuncSetAttribute(gemm_out, cudaFuncAttributeMaxDynamicSharedMemorySize, G_SMEM);
    cudaFuncSetAttribute(attn_mma, cudaFuncAttributeMaxDynamicSharedMemorySize, ATT_SMEM);

    dim3 blk(256);

    // ---- stage 1: all plane conversions, one launch
    cvt_all<<<dim3(MKV * E_DIM / 8 / 256, 6), blk>>>(
        x1, x2, Wq, Wk, Wv, Wo,
        x1h, x2h, wqh, wkh, wvh, woh);

    // ---- stage 2: fused Q/K/V projections, one launch
    gemm_qkv<<<dim3(8, MKV / 128, 3), blk, G_SMEM>>>(
        x1h, x2h, wqh, wkh, wvh,
        bq, bk, bv,
        qh, kh, vh);

    // ---- stage 3: attention
    attn_mma<<<dim3(SQ / 128, N_HEADS, BATCH), blk, ATT_SMEM>>>(
        qh, kh, vh, ah);

    // ---- stage 4: output projection (fp32 out)
    gemm_out<<<dim3(8, MQ / 128), blk, G_SMEM>>>(ah, woh, bo, out);
}

// round 14
// speedup vs baseline: 1.5088x; 1.5088x over previous
#include <cuda_runtime.h>
#include <cuda_fp16.h>
#include <cstdint>
#include <math.h>

// Problem constants
#define E_DIM   1024
#define N_HEADS 16
#define H_DIM   64
#define BATCH   4
#define SQ      1024
#define SKV     2048
#define MQ      (BATCH * SQ)    // 4096
#define MKV     (BATCH * SKV)   // 8192

// ---------------------------------------------------------------------------
// Persistent planes (device globals). All single fp16 planes.
// ---------------------------------------------------------------------------
__device__ __align__(16) uint16_t g_x1h[MQ * E_DIM];
__device__ __align__(16) uint16_t g_x2h[MKV * E_DIM];
__device__ __align__(16) uint16_t g_wqh[E_DIM * E_DIM];
__device__ __align__(16) uint16_t g_wkh[E_DIM * E_DIM];
__device__ __align__(16) uint16_t g_wvh[E_DIM * E_DIM];
__device__ __align__(16) uint16_t g_woh[E_DIM * E_DIM];
__device__ __align__(16) uint16_t g_qh[MQ * E_DIM];
__device__ __align__(16) uint16_t g_kh[MKV * E_DIM];
__device__ __align__(16) uint16_t g_vh[MKV * E_DIM];
__device__ __align__(16) uint16_t g_ah[MQ * E_DIM];

// ---------------------------------------------------------------------------
// Helpers
// ---------------------------------------------------------------------------
#define SMEM_SWIZZLE_128B(off) ((off) ^ (((off) >> 3) & 0x70))
#define SMEM_SWIZZLE_64B(off)  ((off) ^ (((off) >> 3) & 0x30))

#define LDSM_X4(r0_,r1_,r2_,r3_,addr_) \
    asm volatile("ldmatrix.sync.aligned.m8n8.x4.shared.b16 {%0,%1,%2,%3}, [%4];" \
        : "=r"(r0_), "=r"(r1_), "=r"(r2_), "=r"(r3_) : "r"(addr_))

#define LDSM_X4_T(r0_,r1_,r2_,r3_,addr_) \
    asm volatile("ldmatrix.sync.aligned.m8n8.x4.trans.shared.b16 {%0,%1,%2,%3}, [%4];" \
        : "=r"(r0_), "=r"(r1_), "=r"(r2_), "=r"(r3_) : "r"(addr_))

#define MMAF16(d_,a_,b_) \
    asm volatile("mma.sync.aligned.m16n8k16.row.col.f32.f16.f16.f32 " \
        "{%0,%1,%2,%3}, {%4,%5,%6,%7}, {%8,%9}, {%0,%1,%2,%3};" \
        : "+f"((d_)[0]), "+f"((d_)[1]), "+f"((d_)[2]), "+f"((d_)[3]) \
        : "r"((a_)[0]), "r"((a_)[1]), "r"((a_)[2]), "r"((a_)[3]), \
          "r"((b_)[0]), "r"((b_)[1]))

#define CP_ASYNC16(dst_, src_) \
    asm volatile("cp.async.cg.shared.global [%0], [%1], 16;" \
        :: "r"(dst_), "l"(src_))
#define CP_COMMIT() asm volatile("cp.async.commit_group;" ::: "memory")
#define CP_WAIT2()  asm volatile("cp.async.wait_group 2;" ::: "memory")
#define CP_WAIT1()  asm volatile("cp.async.wait_group 1;" ::: "memory")
#define CP_WAIT0()  asm volatile("cp.async.wait_group 0;" ::: "memory")

__device__ __forceinline__ uint32_t packh2(float x, float y) {
    __half2 t = __floats2half2_rn(x, y);
    return *(uint32_t*)&t;
}

// ---------------------------------------------------------------------------
// ALL fp32 -> single fp16 plane conversions in ONE launch. grid.y = tensor.
// ---------------------------------------------------------------------------
__global__ void __launch_bounds__(256) cvt_all(
    const float* __restrict__ x1, const float* __restrict__ x2,
    const float* __restrict__ w0, const float* __restrict__ w1,
    const float* __restrict__ w2, const float* __restrict__ w3,
    uint16_t* __restrict__ x1h, uint16_t* __restrict__ x2h,
    uint16_t* __restrict__ h0, uint16_t* __restrict__ h1,
    uint16_t* __restrict__ h2, uint16_t* __restrict__ h3)
{
    const int m = blockIdx.y;
    const int idx = blockIdx.x * 256 + threadIdx.x;
    const float* in; uint16_t* hi; int n8;
    switch (m) {
        case 0: in = x1; hi = x1h; n8 = MQ  * E_DIM / 8; break;
        case 1: in = x2; hi = x2h; n8 = MKV * E_DIM / 8; break;
        case 2: in = w0; hi = h0;  n8 = E_DIM * E_DIM / 8; break;
        case 3: in = w1; hi = h1;  n8 = E_DIM * E_DIM / 8; break;
        case 4: in = w2; hi = h2;  n8 = E_DIM * E_DIM / 8; break;
        default:in = w3; hi = h3;  n8 = E_DIM * E_DIM / 8; break;
    }
    if (idx >= n8) return;
    const float4 f0 = ((const float4*)in)[2 * idx];
    const float4 f1 = ((const float4*)in)[2 * idx + 1];
    uint4 h;
    h.x = packh2(f0.x, f0.y); h.y = packh2(f0.z, f0.w);
    h.z = packh2(f1.x, f1.y); h.w = packh2(f1.z, f1.w);
    ((uint4*)hi)[idx] = h;
}

// ---------------------------------------------------------------------------
// fp16 HMMA GEMM body (single-B): C = A @ B^T (+bias)(*scale), 1 MMA/k-step.
// 4-stage cp.async ring (16KB/stage = 64KB smem, 2 CTAs/SM), power-of-2
// stage indexing (& 3), one chunk per __syncthreads — the R12-proven loop.
// wmode: 0 = fp32 out, 3 = fp16 single plane
// ---------------------------------------------------------------------------
#define GS_A    0
#define GS_B    8192
#define G_STAGE 16384
#define G_SMEM  65536       // 4 stages
#define G_NCHUNK 32

template<int WMODE>
__device__ __forceinline__ void gemm_body(
    const uint16_t* __restrict__ Ah, const uint16_t* __restrict__ Bh,
    const float* __restrict__ bias, float scale,
    float* __restrict__ Cf, uint16_t* __restrict__ Ch,
    char* smem, const int m0, const int n0)
{
    const uint32_t sb = (uint32_t)__cvta_generic_to_shared(smem);
    const int tid  = threadIdx.x;
    const int wid  = tid >> 5;
    const int lane = tid & 31;

    const int warp_m = (wid & 1) * 64;
    const int warp_n = (wid >> 1) * 32;
    const int g = lane >> 3;
    const int r = lane & 7;

    float acc[4][4][4];
#pragma unroll
    for (int mi = 0; mi < 4; mi++)
#pragma unroll
        for (int ni = 0; ni < 4; ni++)
#pragma unroll
            for (int q = 0; q < 4; q++) acc[mi][ni][q] = 0.f;

    const int a_row = warp_m + (g & 1) * 8 + r;
    const int a_kc  = (g >> 1) * 8;
    const int b_row = warp_n + (g >> 1) * 8 + r;
    const int b_kc  = (g & 1) * 8;

    auto load_stage = [&](int stage, int ch) {
        const uint32_t sbase = sb + stage * G_STAGE;
#pragma unroll
        for (int it = 0; it < 2; it++) {
            const int idx = it * 256 + tid;     // 0..511
            const int row = idx >> 2;           // 0..127
            const int seg = idx & 3;            // 16B segment
            const uint32_t sw = SMEM_SWIZZLE_64B((uint32_t)(row * 64 + seg * 16));
            const size_t ga = (size_t)(m0 + row) * E_DIM + ch * 32 + seg * 8;
            const size_t gb = (size_t)(n0 + row) * E_DIM + ch * 32 + seg * 8;
            CP_ASYNC16(sbase + GS_A + sw, (const char*)(Ah + ga));
            CP_ASYNC16(sbase + GS_B + sw, (const char*)(Bh + gb));
        }
    };

    load_stage(0, 0); CP_COMMIT();
    load_stage(1, 1); CP_COMMIT();
    load_stage(2, 2); CP_COMMIT();

    for (int ch = 0; ch < G_NCHUNK; ch++) {
        if (ch < G_NCHUNK - 2) CP_WAIT2(); else CP_WAIT0();
        __syncthreads();
        if (ch + 3 < G_NCHUNK) { load_stage((ch + 3) & 3, ch + 3); CP_COMMIT(); }

        const uint32_t sbase = sb + (ch & 3) * G_STAGE;
#pragma unroll
        for (int ks = 0; ks < 2; ks++) {
            uint32_t ah[4][4];
#pragma unroll
            for (int mi = 0; mi < 4; mi++) {
                const uint32_t sw = SMEM_SWIZZLE_64B(
                    (uint32_t)((a_row + mi * 16) * 64 + (a_kc + ks * 16) * 2));
                LDSM_X4(ah[mi][0], ah[mi][1], ah[mi][2], ah[mi][3], sbase + GS_A + sw);
            }
            uint32_t bh[4][2];
#pragma unroll
            for (int np = 0; np < 2; np++) {
                const uint32_t sw = SMEM_SWIZZLE_64B(
                    (uint32_t)((b_row + np * 16) * 64 + (b_kc + ks * 16) * 2));
                LDSM_X4(bh[2*np][0], bh[2*np][1], bh[2*np+1][0], bh[2*np+1][1],
                        sbase + GS_B + sw);
            }
#pragma unroll
            for (int mi = 0; mi < 4; mi++)
#pragma unroll
                for (int ni = 0; ni < 4; ni++)
                    MMAF16(acc[mi][ni], ah[mi], bh[ni]);
        }
    }

    // ---- epilogue
    const int erow = lane >> 2;
    const int ecol = (lane & 3) * 2;
#pragma unroll
    for (int ni = 0; ni < 4; ni++) {
        const int col = n0 + warp_n + ni * 8 + ecol;
        const float bv0 = __ldg(bias + col);
        const float bv1 = __ldg(bias + col + 1);
#pragma unroll
        for (int mi = 0; mi < 4; mi++) {
            const int row = m0 + warp_m + mi * 16 + erow;
            float v00 = (acc[mi][ni][0] + bv0) * scale;
            float v01 = (acc[mi][ni][1] + bv1) * scale;
            float v10 = (acc[mi][ni][2] + bv0) * scale;
            float v11 = (acc[mi][ni][3] + bv1) * scale;
            if (WMODE == 3) {
                *(uint32_t*)(Ch + (size_t)row * E_DIM + col)       = packh2(v00, v01);
                *(uint32_t*)(Ch + (size_t)(row + 8) * E_DIM + col) = packh2(v10, v11);
            } else {
                float2 a = {v00, v01}, b = {v10, v11};
                *(float2*)(Cf + (size_t)row * E_DIM + col)       = a;
                *(float2*)(Cf + (size_t)(row + 8) * E_DIM + col) = b;
            }
        }
    }
}

// ---- fused Q/K/V projections: grid (8, 64, 3); z=0 uses only y<32
__global__ void __launch_bounds__(256, 2) gemm_qkv(
    const uint16_t* __restrict__ x1h, const uint16_t* __restrict__ x2h,
    const uint16_t* __restrict__ wqh, const uint16_t* __restrict__ wkh,
    const uint16_t* __restrict__ wvh,
    const float* __restrict__ bq, const float* __restrict__ bk,
    const float* __restrict__ bv,
    uint16_t* __restrict__ qh, uint16_t* __restrict__ kh,
    uint16_t* __restrict__ vh)
{
    extern __shared__ char smem[];
    const int z = blockIdx.z;
    if (z == 0 && blockIdx.y >= MQ / 128) return;
    if (z == 0) {
        gemm_body<3>(x1h, wqh, bq, 0.125f, nullptr, qh,
                     smem, blockIdx.y * 128, blockIdx.x * 128);
    } else if (z == 1) {
        gemm_body<3>(x2h, wkh, bk, 1.0f, nullptr, kh,
                     smem, blockIdx.y * 128, blockIdx.x * 128);
    } else {
        gemm_body<3>(x2h, wvh, bv, 1.0f, nullptr, vh,
                     smem, blockIdx.y * 128, blockIdx.x * 128);
    }
}

// ---- output projection (fp32 out)
__global__ void __launch_bounds__(256, 2) gemm_out(
    const uint16_t* __restrict__ Ah, const uint16_t* __restrict__ Bh,
    const float* __restrict__ bias, float* __restrict__ Cf)
{
    extern __shared__ char smem[];
    gemm_body<0>(Ah, Bh, bias, 1.0f, Cf, nullptr,
                 smem, blockIdx.y * 128, blockIdx.x * 128);
}

// ---------------------------------------------------------------------------
// Flash attention v2 on fp16 HMMA. All operands single fp16 planes:
//   S = Q*K (1 MMA); PV = P*V (1 MMA). fp32 acc + softmax.
// CTA = (b, h, 128 q rows); 8 warps x 16 q rows. KV chunk 64, double-buffered.
// ---------------------------------------------------------------------------
#define AS_Q    0          // 128 rows x 128B = 16KB
#define AS_KV   16384      // stage base
#define AS_K    0
#define AS_V    8192
#define A_STAGE 16384
#define ATT_SMEM 49152     // 16KB Q + 2 x 16KB KV
#define NEG_BIG (-3.0e38f)

__global__ void __launch_bounds__(256, 2) attn_mma(
    const uint16_t* __restrict__ Qh,
    const uint16_t* __restrict__ Kh,
    const uint16_t* __restrict__ Vh,
    uint16_t* __restrict__ Oh)
{
    extern __shared__ char smem[];
    const uint32_t sb = (uint32_t)__cvta_generic_to_shared(smem);
    const int b  = blockIdx.z;
    const int h  = blockIdx.y;
    const int q0 = blockIdx.x * 128;
    const int tid  = threadIdx.x;
    const int wid  = tid >> 5;
    const int lane = tid & 31;
    const int g = lane >> 3;
    const int r = lane & 7;

    // ---- Q tile 128x64 via cp.async
#pragma unroll
    for (int it = 0; it < 4; it++) {
        const int idx = it * 256 + tid;
        const int row = idx >> 3;
        const int seg = idx & 7;
        const uint32_t sw = SMEM_SWIZZLE_128B((uint32_t)(row * 128 + seg * 16));
        const size_t gq = (size_t)(b * SQ + q0 + row) * E_DIM + h * H_DIM + seg * 8;
        CP_ASYNC16(sb + AS_Q + sw, (const char*)(Qh + gq));
    }
    CP_COMMIT();

    auto load_kv = [&](int stage, int c) {
        const uint32_t sbase = sb + AS_KV + stage * A_STAGE;
#pragma unroll
        for (int it = 0; it < 2; it++) {
            const int idx = it * 256 + tid;
            const int row = idx >> 3;
            const int seg = idx & 7;
            const uint32_t sw = SMEM_SWIZZLE_128B((uint32_t)(row * 128 + seg * 16));
            const size_t gk = (size_t)(b * SKV + c + row) * E_DIM + h * H_DIM + seg * 8;
            CP_ASYNC16(sbase + AS_K + sw, (const char*)(Kh + gk));
            CP_ASYNC16(sbase + AS_V + sw, (const char*)(Vh + gk));
        }
    };

    load_kv(0, 0);
    CP_COMMIT();
    CP_WAIT1();          // Q ready
    __syncthreads();

    // ---- persistent Q fragments
    const int a_row = wid * 16 + (g & 1) * 8 + r;
    const int a_kc  = (g >> 1) * 8;
    uint32_t qf[4][4];
#pragma unroll
    for (int ks = 0; ks < 4; ks++) {
        const uint32_t sw = SMEM_SWIZZLE_128B((uint32_t)(a_row * 128 + (a_kc + ks * 16) * 2));
        LDSM_X4(qf[ks][0], qf[ks][1], qf[ks][2], qf[ks][3], sb + AS_Q + sw);
    }

    float o[8][4];
#pragma unroll
    for (int na = 0; na < 8; na++)
#pragma unroll
        for (int q = 0; q < 4; q++) o[na][q] = 0.f;
    float mr0 = NEG_BIG, mr1 = NEG_BIG, lr0 = 0.f, lr1 = 0.f;

    const int kb_row = (g >> 1) * 8 + r;
    const int kb_kc  = (g & 1) * 8;

    const int NCH = SKV / 64;   // 32
    for (int cc = 0; cc < NCH; cc++) {
        const int buf = cc & 1;
        if (cc + 1 < NCH) { load_kv(buf ^ 1, (cc + 1) * 64); CP_COMMIT(); CP_WAIT1(); }
        else              { CP_WAIT0(); }
        __syncthreads();
        const uint32_t kvb = sb + AS_KV + buf * A_STAGE;

        // ---- S = Q K^T (fp16 x1)
        float s[8][4];
#pragma unroll
        for (int na = 0; na < 8; na++)
#pragma unroll
            for (int q = 0; q < 4; q++) s[na][q] = 0.f;

#pragma unroll
        for (int ks = 0; ks < 4; ks++) {
            uint32_t kf[8][2];
#pragma unroll
            for (int np = 0; np < 4; np++) {
                const uint32_t sw = SMEM_SWIZZLE_128B(
                    (uint32_t)((np * 16 + kb_row) * 128 + (kb_kc + ks * 16) * 2));
                LDSM_X4(kf[2*np][0], kf[2*np][1], kf[2*np+1][0], kf[2*np+1][1],
                        kvb + AS_K + sw);
            }
#pragma unroll
            for (int na = 0; na < 8; na++) {
                MMAF16(s[na], qf[ks], kf[na]);
            }
        }

        // ---- online softmax
        float mx0 = NEG_BIG, mx1 = NEG_BIG;
#pragma unroll
        for (int na = 0; na < 8; na++) {
            mx0 = fmaxf(mx0, fmaxf(s[na][0], s[na][1]));
            mx1 = fmaxf(mx1, fmaxf(s[na][2], s[na][3]));
        }
        mx0 = fmaxf(mx0, __shfl_xor_sync(0xffffffffu, mx0, 1));
        mx0 = fmaxf(mx0, __shfl_xor_sync(0xffffffffu, mx0, 2));
        mx1 = fmaxf(mx1, __shfl_xor_sync(0xffffffffu, mx1, 1));
        mx1 = fmaxf(mx1, __shfl_xor_sync(0xffffffffu, mx1, 2));
        const float mn0 = fmaxf(mr0, mx0);
        const float mn1 = fmaxf(mr1, mx1);
        const float al0 = __expf(mr0 - mn0);
        const float al1 = __expf(mr1 - mn1);
        mr0 = mn0; mr1 = mn1;
        float ls0 = 0.f, ls1 = 0.f;
#pragma unroll
        for (int na = 0; na < 8; na++) {
            s[na][0] = __expf(s[na][0] - mn0);
            s[na][1] = __expf(s[na][1] - mn0);
            s[na][2] = __expf(s[na][2] - mn1);
            s[na][3] = __expf(s[na][3] - mn1);
            ls0 += s[na][0] + s[na][1];
            ls1 += s[na][2] + s[na][3];
        }
        ls0 += __shfl_xor_sync(0xffffffffu, ls0, 1);
        ls0 += __shfl_xor_sync(0xffffffffu, ls0, 2);
        ls1 += __shfl_xor_sync(0xffffffffu, ls1, 1);
        ls1 += __shfl_xor_sync(0xffffffffu, ls1, 2);
        lr0 = lr0 * al0 + ls0;
        lr1 = lr1 * al1 + ls1;
#pragma unroll
        for (int na = 0; na < 8; na++) {
            o[na][0] *= al0; o[na][1] *= al0;
            o[na][2] *= al1; o[na][3] *= al1;
        }

        // ---- P @ V (fp16 x1)
#pragma unroll
        for (int kt = 0; kt < 4; kt++) {
            uint32_t ph[4];
            ph[0] = packh2(s[2*kt][0],   s[2*kt][1]);
            ph[1] = packh2(s[2*kt][2],   s[2*kt][3]);
            ph[2] = packh2(s[2*kt+1][0], s[2*kt+1][1]);
            ph[3] = packh2(s[2*kt+1][2], s[2*kt+1][3]);

            uint32_t vf[8][2];
#pragma unroll
            for (int dp = 0; dp < 4; dp++) {
                const uint32_t byte = (uint32_t)((kt * 16 + (lane & 15)) * 128
                                                 + dp * 32 + (lane >> 4) * 16);
                const uint32_t sw = SMEM_SWIZZLE_128B(byte);
                LDSM_X4_T(vf[2*dp][0], vf[2*dp][1], vf[2*dp+1][0], vf[2*dp+1][1],
                          kvb + AS_V + sw);
            }
#pragma unroll
            for (int na = 0; na < 8; na++) {
                MMAF16(o[na], ph, vf[na]);
            }
        }
        __syncthreads();
    }

    // ---- epilogue: normalize, write single fp16 plane
    const float inv0 = 1.f / lr0;
    const float inv1 = 1.f / lr1;
    const int row0 = q0 + wid * 16 + (lane >> 2);
#pragma unroll
    for (int na = 0; na < 8; na++) {
        const int col = h * H_DIM + na * 8 + (lane & 3) * 2;
        const size_t i0 = (size_t)(b * SQ + row0) * E_DIM + col;
        const size_t i1 = (size_t)(b * SQ + row0 + 8) * E_DIM + col;
        *(uint32_t*)(Oh + i0) = packh2(o[na][0] * inv0, o[na][1] * inv0);
        *(uint32_t*)(Oh + i1) = packh2(o[na][2] * inv1, o[na][3] * inv1);
    }
}

// ---------------------------------------------------------------------------
extern "C" void kernel_launch(void* const* d_in, const int* in_sizes, int n_in,
                              void* d_out, int out_size)
{
    const float* x1 = (const float*)d_in[0];
    const float* x2 = (const float*)d_in[1];
    const float* Wq = (const float*)d_in[2];
    const float* bq = (const float*)d_in[3];
    const float* Wk = (const float*)d_in[4];
    const float* bk = (const float*)d_in[5];
    const float* Wv = (const float*)d_in[6];
    const float* bv = (const float*)d_in[7];
    const float* Wo = (const float*)d_in[8];
    const float* bo = (const float*)d_in[9];
    float* out = (float*)d_out;

    uint16_t *x1h, *x2h;
    uint16_t *wqh, *wkh, *wvh, *woh;
    uint16_t *qh, *kh, *vh, *ah;
    cudaGetSymbolAddress((void**)&x1h, g_x1h);
    cudaGetSymbolAddress((void**)&x2h, g_x2h);
    cudaGetSymbolAddress((void**)&wqh, g_wqh);
    cudaGetSymbolAddress((void**)&wkh, g_wkh);
    cudaGetSymbolAddress((void**)&wvh, g_wvh);
    cudaGetSymbolAddress((void**)&woh, g_woh);
    cudaGetSymbolAddress((void**)&qh,  g_qh);
    cudaGetSymbolAddress((void**)&kh,  g_kh);
    cudaGetSymbolAddress((void**)&vh,  g_vh);
    cudaGetSymbolAddress((void**)&ah,  g_ah);

    cudaFuncSetAttribute(gemm_qkv, cudaFuncAttributeMaxDynamicSharedMemorySize, G_SMEM);
    cudaFuncSetAttribute(gemm_out, cudaFuncAttributeMaxDynamicSharedMemorySize, G_SMEM);
    cudaFuncSetAttribute(attn_mma, cudaFuncAttributeMaxDynamicSharedMemorySize, ATT_SMEM);

    dim3 blk(256);

    // ---- stage 1: all plane conversions, one launch
    cvt_all<<<dim3(MKV * E_DIM / 8 / 256, 6), blk>>>(
        x1, x2, Wq, Wk, Wv, Wo,
        x1h, x2h, wqh, wkh, wvh, woh);

    // ---- stage 2: fused Q/K/V projections, one launch
    gemm_qkv<<<dim3(8, MKV / 128, 3), blk, G_SMEM>>>(
        x1h, x2h, wqh, wkh, wvh,
        bq, bk, bv,
        qh, kh, vh);

    // ---- stage 3: attention
    attn_mma<<<dim3(SQ / 128, N_HEADS, BATCH), blk, ATT_SMEM>>>(
        qh, kh, vh, ah);

    // ---- stage 4: output projection (fp32 out)
    gemm_out<<<dim3(8, MQ / 128), blk, G_SMEM>>>(ah, woh, bo, out);
}

// round 15
// speedup vs baseline: 1.5640x; 1.0366x over previous
#include <cuda_runtime.h>
#include <cuda_fp16.h>
#include <cstdint>
#include <math.h>

// Problem constants
#define E_DIM   1024
#define N_HEADS 16
#define H_DIM   64
#define BATCH   4
#define SQ      1024
#define SKV     2048
#define MQ      (BATCH * SQ)    // 4096
#define MKV     (BATCH * SKV)   // 8192

// ---------------------------------------------------------------------------
// Persistent planes (device globals). All single fp16 planes.
// ---------------------------------------------------------------------------
__device__ __align__(16) uint16_t g_x1h[MQ * E_DIM];
__device__ __align__(16) uint16_t g_x2h[MKV * E_DIM];
__device__ __align__(16) uint16_t g_wqh[E_DIM * E_DIM];
__device__ __align__(16) uint16_t g_wkh[E_DIM * E_DIM];
__device__ __align__(16) uint16_t g_wvh[E_DIM * E_DIM];
__device__ __align__(16) uint16_t g_woh[E_DIM * E_DIM];
__device__ __align__(16) uint16_t g_qh[MQ * E_DIM];
__device__ __align__(16) uint16_t g_kh[MKV * E_DIM];
__device__ __align__(16) uint16_t g_vh[MKV * E_DIM];
__device__ __align__(16) uint16_t g_ah[MQ * E_DIM];

// ---------------------------------------------------------------------------
// Helpers
// ---------------------------------------------------------------------------
#define SMEM_SWIZZLE_128B(off) ((off) ^ (((off) >> 3) & 0x70))
#define SMEM_SWIZZLE_64B(off)  ((off) ^ (((off) >> 3) & 0x30))

#define LDSM_X4(r0_,r1_,r2_,r3_,addr_) \
    asm volatile("ldmatrix.sync.aligned.m8n8.x4.shared.b16 {%0,%1,%2,%3}, [%4];" \
        : "=r"(r0_), "=r"(r1_), "=r"(r2_), "=r"(r3_) : "r"(addr_))

#define LDSM_X4_T(r0_,r1_,r2_,r3_,addr_) \
    asm volatile("ldmatrix.sync.aligned.m8n8.x4.trans.shared.b16 {%0,%1,%2,%3}, [%4];" \
        : "=r"(r0_), "=r"(r1_), "=r"(r2_), "=r"(r3_) : "r"(addr_))

#define MMAF16(d_,a_,b_) \
    asm volatile("mma.sync.aligned.m16n8k16.row.col.f32.f16.f16.f32 " \
        "{%0,%1,%2,%3}, {%4,%5,%6,%7}, {%8,%9}, {%0,%1,%2,%3};" \
        : "+f"((d_)[0]), "+f"((d_)[1]), "+f"((d_)[2]), "+f"((d_)[3]) \
        : "r"((a_)[0]), "r"((a_)[1]), "r"((a_)[2]), "r"((a_)[3]), \
          "r"((b_)[0]), "r"((b_)[1]))

#define CP_ASYNC16(dst_, src_) \
    asm volatile("cp.async.cg.shared.global [%0], [%1], 16;" \
        :: "r"(dst_), "l"(src_))
#define CP_COMMIT() asm volatile("cp.async.commit_group;" ::: "memory")
#define CP_WAIT2()  asm volatile("cp.async.wait_group 2;" ::: "memory")
#define CP_WAIT1()  asm volatile("cp.async.wait_group 1;" ::: "memory")
#define CP_WAIT0()  asm volatile("cp.async.wait_group 0;" ::: "memory")

__device__ __forceinline__ uint32_t packh2(float x, float y) {
    __half2 t = __floats2half2_rn(x, y);
    return *(uint32_t*)&t;
}

// ---------------------------------------------------------------------------
// ALL fp32 -> single fp16 plane conversions in ONE launch. grid.y = tensor.
// ---------------------------------------------------------------------------
__global__ void __launch_bounds__(256) cvt_all(
    const float* __restrict__ x1, const float* __restrict__ x2,
    const float* __restrict__ w0, const float* __restrict__ w1,
    const float* __restrict__ w2, const float* __restrict__ w3,
    uint16_t* __restrict__ x1h, uint16_t* __restrict__ x2h,
    uint16_t* __restrict__ h0, uint16_t* __restrict__ h1,
    uint16_t* __restrict__ h2, uint16_t* __restrict__ h3)
{
    const int m = blockIdx.y;
    const int idx = blockIdx.x * 256 + threadIdx.x;
    const float* in; uint16_t* hi; int n8;
    switch (m) {
        case 0: in = x1; hi = x1h; n8 = MQ  * E_DIM / 8; break;
        case 1: in = x2; hi = x2h; n8 = MKV * E_DIM / 8; break;
        case 2: in = w0; hi = h0;  n8 = E_DIM * E_DIM / 8; break;
        case 3: in = w1; hi = h1;  n8 = E_DIM * E_DIM / 8; break;
        case 4: in = w2; hi = h2;  n8 = E_DIM * E_DIM / 8; break;
        default:in = w3; hi = h3;  n8 = E_DIM * E_DIM / 8; break;
    }
    if (idx >= n8) return;
    const float4 f0 = ((const float4*)in)[2 * idx];
    const float4 f1 = ((const float4*)in)[2 * idx + 1];
    uint4 h;
    h.x = packh2(f0.x, f0.y); h.y = packh2(f0.z, f0.w);
    h.z = packh2(f1.x, f1.y); h.w = packh2(f1.z, f1.w);
    ((uint4*)hi)[idx] = h;
}

// ---------------------------------------------------------------------------
// fp16 HMMA GEMM body (single-B): C = A @ B^T (+bias)(*scale), 1 MMA/k-step.
// 4-stage cp.async ring (16KB/stage = 64KB smem, 2 CTAs/SM), & 3 indexing,
// one chunk per __syncthreads — the R12/R14-proven loop. UNCHANGED.
// wmode: 0 = fp32 out, 3 = fp16 single plane
// ---------------------------------------------------------------------------
#define GS_A    0
#define GS_B    8192
#define G_STAGE 16384
#define G_SMEM  65536       // 4 stages
#define G_NCHUNK 32

template<int WMODE>
__device__ __forceinline__ void gemm_body(
    const uint16_t* __restrict__ Ah, const uint16_t* __restrict__ Bh,
    const float* __restrict__ bias, float scale,
    float* __restrict__ Cf, uint16_t* __restrict__ Ch,
    char* smem, const int m0, const int n0)
{
    const uint32_t sb = (uint32_t)__cvta_generic_to_shared(smem);
    const int tid  = threadIdx.x;
    const int wid  = tid >> 5;
    const int lane = tid & 31;

    const int warp_m = (wid & 1) * 64;
    const int warp_n = (wid >> 1) * 32;
    const int g = lane >> 3;
    const int r = lane & 7;

    float acc[4][4][4];
#pragma unroll
    for (int mi = 0; mi < 4; mi++)
#pragma unroll
        for (int ni = 0; ni < 4; ni++)
#pragma unroll
            for (int q = 0; q < 4; q++) acc[mi][ni][q] = 0.f;

    const int a_row = warp_m + (g & 1) * 8 + r;
    const int a_kc  = (g >> 1) * 8;
    const int b_row = warp_n + (g >> 1) * 8 + r;
    const int b_kc  = (g & 1) * 8;

    auto load_stage = [&](int stage, int ch) {
        const uint32_t sbase = sb + stage * G_STAGE;
#pragma unroll
        for (int it = 0; it < 2; it++) {
            const int idx = it * 256 + tid;     // 0..511
            const int row = idx >> 2;           // 0..127
            const int seg = idx & 3;            // 16B segment
            const uint32_t sw = SMEM_SWIZZLE_64B((uint32_t)(row * 64 + seg * 16));
            const size_t ga = (size_t)(m0 + row) * E_DIM + ch * 32 + seg * 8;
            const size_t gb = (size_t)(n0 + row) * E_DIM + ch * 32 + seg * 8;
            CP_ASYNC16(sbase + GS_A + sw, (const char*)(Ah + ga));
            CP_ASYNC16(sbase + GS_B + sw, (const char*)(Bh + gb));
        }
    };

    load_stage(0, 0); CP_COMMIT();
    load_stage(1, 1); CP_COMMIT();
    load_stage(2, 2); CP_COMMIT();

    for (int ch = 0; ch < G_NCHUNK; ch++) {
        if (ch < G_NCHUNK - 2) CP_WAIT2(); else CP_WAIT0();
        __syncthreads();
        if (ch + 3 < G_NCHUNK) { load_stage((ch + 3) & 3, ch + 3); CP_COMMIT(); }

        const uint32_t sbase = sb + (ch & 3) * G_STAGE;
#pragma unroll
        for (int ks = 0; ks < 2; ks++) {
            uint32_t ah[4][4];
#pragma unroll
            for (int mi = 0; mi < 4; mi++) {
                const uint32_t sw = SMEM_SWIZZLE_64B(
                    (uint32_t)((a_row + mi * 16) * 64 + (a_kc + ks * 16) * 2));
                LDSM_X4(ah[mi][0], ah[mi][1], ah[mi][2], ah[mi][3], sbase + GS_A + sw);
            }
            uint32_t bh[4][2];
#pragma unroll
            for (int np = 0; np < 2; np++) {
                const uint32_t sw = SMEM_SWIZZLE_64B(
                    (uint32_t)((b_row + np * 16) * 64 + (b_kc + ks * 16) * 2));
                LDSM_X4(bh[2*np][0], bh[2*np][1], bh[2*np+1][0], bh[2*np+1][1],
                        sbase + GS_B + sw);
            }
#pragma unroll
            for (int mi = 0; mi < 4; mi++)
#pragma unroll
                for (int ni = 0; ni < 4; ni++)
                    MMAF16(acc[mi][ni], ah[mi], bh[ni]);
        }
    }

    // ---- epilogue
    const int erow = lane >> 2;
    const int ecol = (lane & 3) * 2;
#pragma unroll
    for (int ni = 0; ni < 4; ni++) {
        const int col = n0 + warp_n + ni * 8 + ecol;
        const float bv0 = __ldg(bias + col);
        const float bv1 = __ldg(bias + col + 1);
#pragma unroll
        for (int mi = 0; mi < 4; mi++) {
            const int row = m0 + warp_m + mi * 16 + erow;
            float v00 = (acc[mi][ni][0] + bv0) * scale;
            float v01 = (acc[mi][ni][1] + bv1) * scale;
            float v10 = (acc[mi][ni][2] + bv0) * scale;
            float v11 = (acc[mi][ni][3] + bv1) * scale;
            if (WMODE == 3) {
                *(uint32_t*)(Ch + (size_t)row * E_DIM + col)       = packh2(v00, v01);
                *(uint32_t*)(Ch + (size_t)(row + 8) * E_DIM + col) = packh2(v10, v11);
            } else {
                float2 a = {v00, v01}, b = {v10, v11};
                *(float2*)(Cf + (size_t)row * E_DIM + col)       = a;
                *(float2*)(Cf + (size_t)(row + 8) * E_DIM + col) = b;
            }
        }
    }
}

// ---- fused Q/K/V projections: grid (8, 64, 3); z=0 uses only y<32
__global__ void __launch_bounds__(256, 2) gemm_qkv(
    const uint16_t* __restrict__ x1h, const uint16_t* __restrict__ x2h,
    const uint16_t* __restrict__ wqh, const uint16_t* __restrict__ wkh,
    const uint16_t* __restrict__ wvh,
    const float* __restrict__ bq, const float* __restrict__ bk,
    const float* __restrict__ bv,
    uint16_t* __restrict__ qh, uint16_t* __restrict__ kh,
    uint16_t* __restrict__ vh)
{
    extern __shared__ char smem[];
    const int z = blockIdx.z;
    if (z == 0 && blockIdx.y >= MQ / 128) return;
    if (z == 0) {
        gemm_body<3>(x1h, wqh, bq, 0.125f, nullptr, qh,
                     smem, blockIdx.y * 128, blockIdx.x * 128);
    } else if (z == 1) {
        gemm_body<3>(x2h, wkh, bk, 1.0f, nullptr, kh,
                     smem, blockIdx.y * 128, blockIdx.x * 128);
    } else {
        gemm_body<3>(x2h, wvh, bv, 1.0f, nullptr, vh,
                     smem, blockIdx.y * 128, blockIdx.x * 128);
    }
}

// ---- output projection (fp32 out)
__global__ void __launch_bounds__(256, 2) gemm_out(
    const uint16_t* __restrict__ Ah, const uint16_t* __restrict__ Bh,
    const float* __restrict__ bias, float* __restrict__ Cf)
{
    extern __shared__ char smem[];
    gemm_body<0>(Ah, Bh, bias, 1.0f, Cf, nullptr,
                 smem, blockIdx.y * 128, blockIdx.x * 128);
}

// ---------------------------------------------------------------------------
// Flash attention v2 on fp16 HMMA, 32 q-rows per warp (2 stacked row-tiles).
// CTA = (b, h, 256 q rows); 8 warps; K/V fragments loaded ONCE per warp and
// reused across both row-tiles (halves LDSM bytes per MMA). 1 CTA/SM (regs).
// ---------------------------------------------------------------------------
#define AS_Q    0          // 256 rows x 128B = 32KB
#define AS_KV   32768      // stage base
#define AS_K    0
#define AS_V    8192
#define A_STAGE 16384
#define ATT_SMEM 65536     // 32KB Q + 2 x 16KB KV
#define NEG_BIG (-3.0e38f)

__global__ void __launch_bounds__(256, 1) attn_mma(
    const uint16_t* __restrict__ Qh,
    const uint16_t* __restrict__ Kh,
    const uint16_t* __restrict__ Vh,
    uint16_t* __restrict__ Oh)
{
    extern __shared__ char smem[];
    const uint32_t sb = (uint32_t)__cvta_generic_to_shared(smem);
    const int b  = blockIdx.z;
    const int h  = blockIdx.y;
    const int q0 = blockIdx.x * 256;
    const int tid  = threadIdx.x;
    const int wid  = tid >> 5;
    const int lane = tid & 31;
    const int g = lane >> 3;
    const int r = lane & 7;

    // ---- Q tile 256x64 via cp.async (32KB)
#pragma unroll
    for (int it = 0; it < 8; it++) {
        const int idx = it * 256 + tid;
        const int row = idx >> 3;            // 0..255
        const int seg = idx & 7;
        const uint32_t sw = SMEM_SWIZZLE_128B((uint32_t)(row * 128 + seg * 16));
        const size_t gq = (size_t)(b * SQ + q0 + row) * E_DIM + h * H_DIM + seg * 8;
        CP_ASYNC16(sb + AS_Q + sw, (const char*)(Qh + gq));
    }
    CP_COMMIT();

    auto load_kv = [&](int stage, int c) {
        const uint32_t sbase = sb + AS_KV + stage * A_STAGE;
#pragma unroll
        for (int it = 0; it < 2; it++) {
            const int idx = it * 256 + tid;
            const int row = idx >> 3;
            const int seg = idx & 7;
            const uint32_t sw = SMEM_SWIZZLE_128B((uint32_t)(row * 128 + seg * 16));
            const size_t gk = (size_t)(b * SKV + c + row) * E_DIM + h * H_DIM + seg * 8;
            CP_ASYNC16(sbase + AS_K + sw, (const char*)(Kh + gk));
            CP_ASYNC16(sbase + AS_V + sw, (const char*)(Vh + gk));
        }
    };

    load_kv(0, 0);
    CP_COMMIT();
    CP_WAIT1();          // Q ready
    __syncthreads();

    // ---- persistent Q fragments: 2 row-tiles x 4 k-steps
    uint32_t qf[2][4][4];
#pragma unroll
    for (int rt = 0; rt < 2; rt++) {
        const int a_row = wid * 32 + rt * 16 + (g & 1) * 8 + r;
        const int a_kc  = (g >> 1) * 8;
#pragma unroll
        for (int ks = 0; ks < 4; ks++) {
            const uint32_t sw = SMEM_SWIZZLE_128B(
                (uint32_t)(a_row * 128 + (a_kc + ks * 16) * 2));
            LDSM_X4(qf[rt][ks][0], qf[rt][ks][1], qf[rt][ks][2], qf[rt][ks][3],
                    sb + AS_Q + sw);
        }
    }

    float o[2][8][4];
#pragma unroll
    for (int rt = 0; rt < 2; rt++)
#pragma unroll
        for (int na = 0; na < 8; na++)
#pragma unroll
            for (int q = 0; q < 4; q++) o[rt][na][q] = 0.f;
    float mr[2][2] = {{NEG_BIG, NEG_BIG}, {NEG_BIG, NEG_BIG}};
    float lr[2][2] = {{0.f, 0.f}, {0.f, 0.f}};

    const int kb_row = (g >> 1) * 8 + r;
    const int kb_kc  = (g & 1) * 8;

    const int NCH = SKV / 64;   // 32
    for (int cc = 0; cc < NCH; cc++) {
        const int buf = cc & 1;
        if (cc + 1 < NCH) { load_kv(buf ^ 1, (cc + 1) * 64); CP_COMMIT(); CP_WAIT1(); }
        else              { CP_WAIT0(); }
        __syncthreads();
        const uint32_t kvb = sb + AS_KV + buf * A_STAGE;

        // ---- S = Q K^T: kf loaded once per ks, used by both row-tiles
        float s[2][8][4];
#pragma unroll
        for (int rt = 0; rt < 2; rt++)
#pragma unroll
            for (int na = 0; na < 8; na++)
#pragma unroll
                for (int q = 0; q < 4; q++) s[rt][na][q] = 0.f;

#pragma unroll
        for (int ks = 0; ks < 4; ks++) {
            uint32_t kf[8][2];
#pragma unroll
            for (int np = 0; np < 4; np++) {
                const uint32_t sw = SMEM_SWIZZLE_128B(
                    (uint32_t)((np * 16 + kb_row) * 128 + (kb_kc + ks * 16) * 2));
                LDSM_X4(kf[2*np][0], kf[2*np][1], kf[2*np+1][0], kf[2*np+1][1],
                        kvb + AS_K + sw);
            }
#pragma unroll
            for (int rt = 0; rt < 2; rt++)
#pragma unroll
                for (int na = 0; na < 8; na++)
                    MMAF16(s[rt][na], qf[rt][ks], kf[na]);
        }

        // ---- online softmax per row-tile
#pragma unroll
        for (int rt = 0; rt < 2; rt++) {
            float mx0 = NEG_BIG, mx1 = NEG_BIG;
#pragma unroll
            for (int na = 0; na < 8; na++) {
                mx0 = fmaxf(mx0, fmaxf(s[rt][na][0], s[rt][na][1]));
                mx1 = fmaxf(mx1, fmaxf(s[rt][na][2], s[rt][na][3]));
            }
            mx0 = fmaxf(mx0, __shfl_xor_sync(0xffffffffu, mx0, 1));
            mx0 = fmaxf(mx0, __shfl_xor_sync(0xffffffffu, mx0, 2));
            mx1 = fmaxf(mx1, __shfl_xor_sync(0xffffffffu, mx1, 1));
            mx1 = fmaxf(mx1, __shfl_xor_sync(0xffffffffu, mx1, 2));
            const float mn0 = fmaxf(mr[rt][0], mx0);
            const float mn1 = fmaxf(mr[rt][1], mx1);
            const float al0 = __expf(mr[rt][0] - mn0);
            const float al1 = __expf(mr[rt][1] - mn1);
            mr[rt][0] = mn0; mr[rt][1] = mn1;
            float ls0 = 0.f, ls1 = 0.f;
#pragma unroll
            for (int na = 0; na < 8; na++) {
                s[rt][na][0] = __expf(s[rt][na][0] - mn0);
                s[rt][na][1] = __expf(s[rt][na][1] - mn0);
                s[rt][na][2] = __expf(s[rt][na][2] - mn1);
                s[rt][na][3] = __expf(s[rt][na][3] - mn1);
                ls0 += s[rt][na][0] + s[rt][na][1];
                ls1 += s[rt][na][2] + s[rt][na][3];
            }
            ls0 += __shfl_xor_sync(0xffffffffu, ls0, 1);
            ls0 += __shfl_xor_sync(0xffffffffu, ls0, 2);
            ls1 += __shfl_xor_sync(0xffffffffu, ls1, 1);
            ls1 += __shfl_xor_sync(0xffffffffu, ls1, 2);
            lr[rt][0] = lr[rt][0] * al0 + ls0;
            lr[rt][1] = lr[rt][1] * al1 + ls1;
#pragma unroll
            for (int na = 0; na < 8; na++) {
                o[rt][na][0] *= al0; o[rt][na][1] *= al0;
                o[rt][na][2] *= al1; o[rt][na][3] *= al1;
            }
        }

        // ---- P @ V: vf loaded once per kt, used by both row-tiles
#pragma unroll
        for (int kt = 0; kt < 4; kt++) {
            uint32_t vf[8][2];
#pragma unroll
            for (int dp = 0; dp < 4; dp++) {
                const uint32_t byte = (uint32_t)((kt * 16 + (lane & 15)) * 128
                                                 + dp * 32 + (lane >> 4) * 16);
                const uint32_t sw = SMEM_SWIZZLE_128B(byte);
                LDSM_X4_T(vf[2*dp][0], vf[2*dp][1], vf[2*dp+1][0], vf[2*dp+1][1],
                          kvb + AS_V + sw);
            }
#pragma unroll
            for (int rt = 0; rt < 2; rt++) {
                uint32_t ph[4];
                ph[0] = packh2(s[rt][2*kt][0],   s[rt][2*kt][1]);
                ph[1] = packh2(s[rt][2*kt][2],   s[rt][2*kt][3]);
                ph[2] = packh2(s[rt][2*kt+1][0], s[rt][2*kt+1][1]);
                ph[3] = packh2(s[rt][2*kt+1][2], s[rt][2*kt+1][3]);
#pragma unroll
                for (int na = 0; na < 8; na++)
                    MMAF16(o[rt][na], ph, vf[na]);
            }
        }
        __syncthreads();
    }

    // ---- epilogue: normalize, write single fp16 plane
#pragma unroll
    for (int rt = 0; rt < 2; rt++) {
        const float inv0 = 1.f / lr[rt][0];
        const float inv1 = 1.f / lr[rt][1];
        const int row0 = q0 + wid * 32 + rt * 16 + (lane >> 2);
#pragma unroll
        for (int na = 0; na < 8; na++) {
            const int col = h * H_DIM + na * 8 + (lane & 3) * 2;
            const size_t i0 = (size_t)(b * SQ + row0) * E_DIM + col;
            const size_t i1 = (size_t)(b * SQ + row0 + 8) * E_DIM + col;
            *(uint32_t*)(Oh + i0) = packh2(o[rt][na][0] * inv0, o[rt][na][1] * inv0);
            *(uint32_t*)(Oh + i1) = packh2(o[rt][na][2] * inv1, o[rt][na][3] * inv1);
        }
    }
}

// ---------------------------------------------------------------------------
extern "C" void kernel_launch(void* const* d_in, const int* in_sizes, int n_in,
                              void* d_out, int out_size)
{
    const float* x1 = (const float*)d_in[0];
    const float* x2 = (const float*)d_in[1];
    const float* Wq = (const float*)d_in[2];
    const float* bq = (const float*)d_in[3];
    const float* Wk = (const float*)d_in[4];
    const float* bk = (const float*)d_in[5];
    const float* Wv = (const float*)d_in[6];
    const float* bv = (const float*)d_in[7];
    const float* Wo = (const float*)d_in[8];
    const float* bo = (const float*)d_in[9];
    float* out = (float*)d_out;

    uint16_t *x1h, *x2h;
    uint16_t *wqh, *wkh, *wvh, *woh;
    uint16_t *qh, *kh, *vh, *ah;
    cudaGetSymbolAddress((void**)&x1h, g_x1h);
    cudaGetSymbolAddress((void**)&x2h, g_x2h);
    cudaGetSymbolAddress((void**)&wqh, g_wqh);
    cudaGetSymbolAddress((void**)&wkh, g_wkh);
    cudaGetSymbolAddress((void**)&wvh, g_wvh);
    cudaGetSymbolAddress((void**)&woh, g_woh);
    cudaGetSymbolAddress((void**)&qh,  g_qh);
    cudaGetSymbolAddress((void**)&kh,  g_kh);
    cudaGetSymbolAddress((void**)&vh,  g_vh);
    cudaGetSymbolAddress((void**)&ah,  g_ah);

    cudaFuncSetAttribute(gemm_qkv, cudaFuncAttributeMaxDynamicSharedMemorySize, G_SMEM);
    cudaFuncSetAttribute(gemm_out, cudaFuncAttributeMaxDynamicSharedMemorySize, G_SMEM);
    cudaFuncSetAttribute(attn_mma, cudaFuncAttributeMaxDynamicSharedMemorySize, ATT_SMEM);

    dim3 blk(256);

    // ---- stage 1: all plane conversions, one launch
    cvt_all<<<dim3(MKV * E_DIM / 8 / 256, 6), blk>>>(
        x1, x2, Wq, Wk, Wv, Wo,
        x1h, x2h, wqh, wkh, wvh, woh);

    // ---- stage 2: fused Q/K/V projections, one launch
    gemm_qkv<<<dim3(8, MKV / 128, 3), blk, G_SMEM>>>(
        x1h, x2h, wqh, wkh, wvh,
        bq, bk, bv,
        qh, kh, vh);

    // ---- stage 3: attention (256 q rows per CTA)
    attn_mma<<<dim3(SQ / 256, N_HEADS, BATCH), blk, ATT_SMEM>>>(
        qh, kh, vh, ah);

    // ---- stage 4: output projection (fp32 out)
    gemm_out<<<dim3(8, MQ / 128), blk, G_SMEM>>>(ah, woh, bo, out);
}

// round 16
// speedup vs baseline: 1.5925x; 1.0182x over previous
#include <cuda_runtime.h>
#include <cuda_fp16.h>
#include <cstdint>
#include <math.h>

// Problem constants
#define E_DIM   1024
#define N_HEADS 16
#define H_DIM   64
#define BATCH   4
#define SQ      1024
#define SKV     2048
#define MQ      (BATCH * SQ)    // 4096
#define MKV     (BATCH * SKV)   // 8192

// ---------------------------------------------------------------------------
// Persistent planes (device globals). All single fp16 planes.
// ---------------------------------------------------------------------------
__device__ __align__(16) uint16_t g_x1h[MQ * E_DIM];
__device__ __align__(16) uint16_t g_x2h[MKV * E_DIM];
__device__ __align__(16) uint16_t g_wqh[E_DIM * E_DIM];
__device__ __align__(16) uint16_t g_wkh[E_DIM * E_DIM];
__device__ __align__(16) uint16_t g_wvh[E_DIM * E_DIM];
__device__ __align__(16) uint16_t g_woh[E_DIM * E_DIM];
__device__ __align__(16) uint16_t g_qh[MQ * E_DIM];
__device__ __align__(16) uint16_t g_kh[MKV * E_DIM];
__device__ __align__(16) uint16_t g_vh[MKV * E_DIM];
__device__ __align__(16) uint16_t g_ah[MQ * E_DIM];

// ---------------------------------------------------------------------------
// Helpers
// ---------------------------------------------------------------------------
#define SMEM_SWIZZLE_128B(off) ((off) ^ (((off) >> 3) & 0x70))
#define SMEM_SWIZZLE_64B(off)  ((off) ^ (((off) >> 3) & 0x30))

#define LDSM_X4(r0_,r1_,r2_,r3_,addr_) \
    asm volatile("ldmatrix.sync.aligned.m8n8.x4.shared.b16 {%0,%1,%2,%3}, [%4];" \
        : "=r"(r0_), "=r"(r1_), "=r"(r2_), "=r"(r3_) : "r"(addr_))

#define LDSM_X4_T(r0_,r1_,r2_,r3_,addr_) \
    asm volatile("ldmatrix.sync.aligned.m8n8.x4.trans.shared.b16 {%0,%1,%2,%3}, [%4];" \
        : "=r"(r0_), "=r"(r1_), "=r"(r2_), "=r"(r3_) : "r"(addr_))

#define MMAF16(d_,a_,b_) \
    asm volatile("mma.sync.aligned.m16n8k16.row.col.f32.f16.f16.f32 " \
        "{%0,%1,%2,%3}, {%4,%5,%6,%7}, {%8,%9}, {%0,%1,%2,%3};" \
        : "+f"((d_)[0]), "+f"((d_)[1]), "+f"((d_)[2]), "+f"((d_)[3]) \
        : "r"((a_)[0]), "r"((a_)[1]), "r"((a_)[2]), "r"((a_)[3]), \
          "r"((b_)[0]), "r"((b_)[1]))

#define CP_ASYNC16(dst_, src_) \
    asm volatile("cp.async.cg.shared.global [%0], [%1], 16;" \
        :: "r"(dst_), "l"(src_))
#define CP_COMMIT() asm volatile("cp.async.commit_group;" ::: "memory")
#define CP_WAIT2()  asm volatile("cp.async.wait_group 2;" ::: "memory")
#define CP_WAIT1()  asm volatile("cp.async.wait_group 1;" ::: "memory")
#define CP_WAIT0()  asm volatile("cp.async.wait_group 0;" ::: "memory")

__device__ __forceinline__ uint32_t packh2(float x, float y) {
    __half2 t = __floats2half2_rn(x, y);
    return *(uint32_t*)&t;
}

// ---------------------------------------------------------------------------
// ALL fp32 -> single fp16 plane conversions, flat 1D grid (no wasted CTAs).
// segment counts (8 floats each): x1 524288 | x2 1048576 | w 131072 x4
// ---------------------------------------------------------------------------
#define CVT_X1_END  524288
#define CVT_X2_END  1572864
#define CVT_TOTAL   2097152

__global__ void __launch_bounds__(256) cvt_all(
    const float* __restrict__ x1, const float* __restrict__ x2,
    const float* __restrict__ w0, const float* __restrict__ w1,
    const float* __restrict__ w2, const float* __restrict__ w3,
    uint16_t* __restrict__ x1h, uint16_t* __restrict__ x2h,
    uint16_t* __restrict__ h0, uint16_t* __restrict__ h1,
    uint16_t* __restrict__ h2, uint16_t* __restrict__ h3)
{
    const int idx = blockIdx.x * 256 + threadIdx.x;
    const float* in; uint16_t* hi; int i;
    if (idx < CVT_X1_END) {
        in = x1; hi = x1h; i = idx;
    } else if (idx < CVT_X2_END) {
        in = x2; hi = x2h; i = idx - CVT_X1_END;
    } else {
        const int w = (idx - CVT_X2_END) >> 17;      // /131072
        i = (idx - CVT_X2_END) & 131071;
        in = (w == 0) ? w0 : (w == 1) ? w1 : (w == 2) ? w2 : w3;
        hi = (w == 0) ? h0 : (w == 1) ? h1 : (w == 2) ? h2 : h3;
    }
    const float4 f0 = ((const float4*)in)[2 * i];
    const float4 f1 = ((const float4*)in)[2 * i + 1];
    uint4 h;
    h.x = packh2(f0.x, f0.y); h.y = packh2(f0.z, f0.w);
    h.z = packh2(f1.x, f1.y); h.w = packh2(f1.z, f1.w);
    ((uint4*)hi)[i] = h;
}

// ---------------------------------------------------------------------------
// fp16 HMMA GEMM body (single-B): 128-thread CTA, 4 warps, warp tile 64x64.
// Per ks: 4 A + 4 B LDSM.x4 feed 32 MMAs (128 B/MMA, was 192).
// 4-stage cp.async ring (16KB/stage = 64KB smem), & 3 indexing, 2 CTAs/SM.
// wmode: 0 = fp32 out, 3 = fp16 single plane
// ---------------------------------------------------------------------------
#define GS_A    0
#define GS_B    8192
#define G_STAGE 16384
#define G_SMEM  65536       // 4 stages
#define G_NCHUNK 32
#define G_THREADS 128

template<int WMODE>
__device__ __forceinline__ void gemm_body(
    const uint16_t* __restrict__ Ah, const uint16_t* __restrict__ Bh,
    const float* __restrict__ bias, float scale,
    float* __restrict__ Cf, uint16_t* __restrict__ Ch,
    char* smem, const int m0, const int n0)
{
    const uint32_t sb = (uint32_t)__cvta_generic_to_shared(smem);
    const int tid  = threadIdx.x;
    const int wid  = tid >> 5;          // 0..3
    const int lane = tid & 31;

    const int warp_m = (wid & 1) * 64;
    const int warp_n = (wid >> 1) * 64;
    const int g = lane >> 3;
    const int r = lane & 7;

    float acc[4][8][4];
#pragma unroll
    for (int mi = 0; mi < 4; mi++)
#pragma unroll
        for (int ni = 0; ni < 8; ni++)
#pragma unroll
            for (int q = 0; q < 4; q++) acc[mi][ni][q] = 0.f;

    const int a_row = warp_m + (g & 1) * 8 + r;
    const int a_kc  = (g >> 1) * 8;
    const int b_row = warp_n + (g >> 1) * 8 + r;   // + np*16
    const int b_kc  = (g & 1) * 8;

    auto load_stage = [&](int stage, int ch) {
        const uint32_t sbase = sb + stage * G_STAGE;
#pragma unroll
        for (int it = 0; it < 4; it++) {
            const int idx = it * G_THREADS + tid;   // 0..511
            const int row = idx >> 2;               // 0..127
            const int seg = idx & 3;                // 16B segment
            const uint32_t sw = SMEM_SWIZZLE_64B((uint32_t)(row * 64 + seg * 16));
            const size_t ga = (size_t)(m0 + row) * E_DIM + ch * 32 + seg * 8;
            const size_t gb = (size_t)(n0 + row) * E_DIM + ch * 32 + seg * 8;
            CP_ASYNC16(sbase + GS_A + sw, (const char*)(Ah + ga));
            CP_ASYNC16(sbase + GS_B + sw, (const char*)(Bh + gb));
        }
    };

    load_stage(0, 0); CP_COMMIT();
    load_stage(1, 1); CP_COMMIT();
    load_stage(2, 2); CP_COMMIT();

    for (int ch = 0; ch < G_NCHUNK; ch++) {
        if (ch < G_NCHUNK - 2) CP_WAIT2(); else CP_WAIT0();
        __syncthreads();
        if (ch + 3 < G_NCHUNK) { load_stage((ch + 3) & 3, ch + 3); CP_COMMIT(); }

        const uint32_t sbase = sb + (ch & 3) * G_STAGE;
#pragma unroll
        for (int ks = 0; ks < 2; ks++) {
            uint32_t ah[4][4];
#pragma unroll
            for (int mi = 0; mi < 4; mi++) {
                const uint32_t sw = SMEM_SWIZZLE_64B(
                    (uint32_t)((a_row + mi * 16) * 64 + (a_kc + ks * 16) * 2));
                LDSM_X4(ah[mi][0], ah[mi][1], ah[mi][2], ah[mi][3], sbase + GS_A + sw);
            }
            uint32_t bh[8][2];
#pragma unroll
            for (int np = 0; np < 4; np++) {
                const uint32_t sw = SMEM_SWIZZLE_64B(
                    (uint32_t)((b_row + np * 16) * 64 + (b_kc + ks * 16) * 2));
                LDSM_X4(bh[2*np][0], bh[2*np][1], bh[2*np+1][0], bh[2*np+1][1],
                        sbase + GS_B + sw);
            }
#pragma unroll
            for (int mi = 0; mi < 4; mi++)
#pragma unroll
                for (int ni = 0; ni < 8; ni++)
                    MMAF16(acc[mi][ni], ah[mi], bh[ni]);
        }
    }

    // ---- epilogue
    const int erow = lane >> 2;
    const int ecol = (lane & 3) * 2;
#pragma unroll
    for (int ni = 0; ni < 8; ni++) {
        const int col = n0 + warp_n + ni * 8 + ecol;
        const float bv0 = __ldg(bias + col);
        const float bv1 = __ldg(bias + col + 1);
#pragma unroll
        for (int mi = 0; mi < 4; mi++) {
            const int row = m0 + warp_m + mi * 16 + erow;
            float v00 = (acc[mi][ni][0] + bv0) * scale;
            float v01 = (acc[mi][ni][1] + bv1) * scale;
            float v10 = (acc[mi][ni][2] + bv0) * scale;
            float v11 = (acc[mi][ni][3] + bv1) * scale;
            if (WMODE == 3) {
                *(uint32_t*)(Ch + (size_t)row * E_DIM + col)       = packh2(v00, v01);
                *(uint32_t*)(Ch + (size_t)(row + 8) * E_DIM + col) = packh2(v10, v11);
            } else {
                float2 a = {v00, v01}, b = {v10, v11};
                *(float2*)(Cf + (size_t)row * E_DIM + col)       = a;
                *(float2*)(Cf + (size_t)(row + 8) * E_DIM + col) = b;
            }
        }
    }
}

// ---- fused Q/K/V projections: grid (8, 64, 3); z=0 uses only y<32
__global__ void __launch_bounds__(G_THREADS, 2) gemm_qkv(
    const uint16_t* __restrict__ x1h, const uint16_t* __restrict__ x2h,
    const uint16_t* __restrict__ wqh, const uint16_t* __restrict__ wkh,
    const uint16_t* __restrict__ wvh,
    const float* __restrict__ bq, const float* __restrict__ bk,
    const float* __restrict__ bv,
    uint16_t* __restrict__ qh, uint16_t* __restrict__ kh,
    uint16_t* __restrict__ vh)
{
    extern __shared__ char smem[];
    const int z = blockIdx.z;
    if (z == 0 && blockIdx.y >= MQ / 128) return;
    if (z == 0) {
        gemm_body<3>(x1h, wqh, bq, 0.125f, nullptr, qh,
                     smem, blockIdx.y * 128, blockIdx.x * 128);
    } else if (z == 1) {
        gemm_body<3>(x2h, wkh, bk, 1.0f, nullptr, kh,
                     smem, blockIdx.y * 128, blockIdx.x * 128);
    } else {
        gemm_body<3>(x2h, wvh, bv, 1.0f, nullptr, vh,
                     smem, blockIdx.y * 128, blockIdx.x * 128);
    }
}

// ---- output projection (fp32 out)
__global__ void __launch_bounds__(G_THREADS, 2) gemm_out(
    const uint16_t* __restrict__ Ah, const uint16_t* __restrict__ Bh,
    const float* __restrict__ bias, float* __restrict__ Cf)
{
    extern __shared__ char smem[];
    gemm_body<0>(Ah, Bh, bias, 1.0f, Cf, nullptr,
                 smem, blockIdx.y * 128, blockIdx.x * 128);
}

// ---------------------------------------------------------------------------
// Flash attention v2 on fp16 HMMA, 32 q-rows per warp (2 stacked row-tiles).
// CTA = (b, h, 256 q rows); 8 warps; KV stage = 128 rows (32KB), processed as
// 2 x 64-row sub-chunks (regs/math identical to chunk-64; barriers halved).
// ---------------------------------------------------------------------------
#define AS_Q    0          // 256 rows x 128B = 32KB
#define AS_KV   32768      // stage base
#define AS_K    0          // 128 rows x 128B = 16KB
#define AS_V    16384
#define A_STAGE 32768
#define ATT_SMEM 98304     // 32KB Q + 2 x 32KB KV
#define NEG_BIG (-3.0e38f)

__global__ void __launch_bounds__(256, 1) attn_mma(
    const uint16_t* __restrict__ Qh,
    const uint16_t* __restrict__ Kh,
    const uint16_t* __restrict__ Vh,
    uint16_t* __restrict__ Oh)
{
    extern __shared__ char smem[];
    const uint32_t sb = (uint32_t)__cvta_generic_to_shared(smem);
    const int b  = blockIdx.z;
    const int h  = blockIdx.y;
    const int q0 = blockIdx.x * 256;
    const int tid  = threadIdx.x;
    const int wid  = tid >> 5;
    const int lane = tid & 31;
    const int g = lane >> 3;
    const int r = lane & 7;

    // ---- Q tile 256x64 via cp.async (32KB)
#pragma unroll
    for (int it = 0; it < 8; it++) {
        const int idx = it * 256 + tid;
        const int row = idx >> 3;            // 0..255
        const int seg = idx & 7;
        const uint32_t sw = SMEM_SWIZZLE_128B((uint32_t)(row * 128 + seg * 16));
        const size_t gq = (size_t)(b * SQ + q0 + row) * E_DIM + h * H_DIM + seg * 8;
        CP_ASYNC16(sb + AS_Q + sw, (const char*)(Qh + gq));
    }
    CP_COMMIT();

    auto load_kv = [&](int stage, int c) {   // loads 128 kv rows
        const uint32_t sbase = sb + AS_KV + stage * A_STAGE;
#pragma unroll
        for (int it = 0; it < 4; it++) {
            const int idx = it * 256 + tid;  // 0..1023
            const int row = idx >> 3;        // 0..127
            const int seg = idx & 7;
            const uint32_t sw = SMEM_SWIZZLE_128B((uint32_t)(row * 128 + seg * 16));
            const size_t gk = (size_t)(b * SKV + c + row) * E_DIM + h * H_DIM + seg * 8;
            CP_ASYNC16(sbase + AS_K + sw, (const char*)(Kh + gk));
            CP_ASYNC16(sbase + AS_V + sw, (const char*)(Vh + gk));
        }
    };

    load_kv(0, 0);
    CP_COMMIT();
    CP_WAIT1();          // Q ready
    __syncthreads();

    // ---- persistent Q fragments: 2 row-tiles x 4 k-steps
    uint32_t qf[2][4][4];
#pragma unroll
    for (int rt = 0; rt < 2; rt++) {
        const int a_row = wid * 32 + rt * 16 + (g & 1) * 8 + r;
        const int a_kc  = (g >> 1) * 8;
#pragma unroll
        for (int ks = 0; ks < 4; ks++) {
            const uint32_t sw = SMEM_SWIZZLE_128B(
                (uint32_t)(a_row * 128 + (a_kc + ks * 16) * 2));
            LDSM_X4(qf[rt][ks][0], qf[rt][ks][1], qf[rt][ks][2], qf[rt][ks][3],
                    sb + AS_Q + sw);
        }
    }

    float o[2][8][4];
#pragma unroll
    for (int rt = 0; rt < 2; rt++)
#pragma unroll
        for (int na = 0; na < 8; na++)
#pragma unroll
            for (int q = 0; q < 4; q++) o[rt][na][q] = 0.f;
    float mr[2][2] = {{NEG_BIG, NEG_BIG}, {NEG_BIG, NEG_BIG}};
    float lr[2][2] = {{0.f, 0.f}, {0.f, 0.f}};

    const int kb_row = (g >> 1) * 8 + r;
    const int kb_kc  = (g & 1) * 8;

    const int NST = SKV / 128;   // 16 stages
    for (int cc = 0; cc < NST; cc++) {
        const int buf = cc & 1;
        if (cc + 1 < NST) { load_kv(buf ^ 1, (cc + 1) * 128); CP_COMMIT(); CP_WAIT1(); }
        else              { CP_WAIT0(); }
        __syncthreads();
        const uint32_t kvb = sb + AS_KV + buf * A_STAGE;

#pragma unroll
        for (int sub = 0; sub < 2; sub++) {
            const uint32_t ksub = kvb + AS_K + sub * 8192;   // 64 rows
            const uint32_t vsub = kvb + AS_V + sub * 8192;

            // ---- S = Q K^T: kf loaded once per ks, used by both row-tiles
            float s[2][8][4];
#pragma unroll
            for (int rt = 0; rt < 2; rt++)
#pragma unroll
                for (int na = 0; na < 8; na++)
#pragma unroll
                    for (int q = 0; q < 4; q++) s[rt][na][q] = 0.f;

#pragma unroll
            for (int ks = 0; ks < 4; ks++) {
                uint32_t kf[8][2];
#pragma unroll
                for (int np = 0; np < 4; np++) {
                    const uint32_t sw = SMEM_SWIZZLE_128B(
                        (uint32_t)((np * 16 + kb_row) * 128 + (kb_kc + ks * 16) * 2));
                    LDSM_X4(kf[2*np][0], kf[2*np][1], kf[2*np+1][0], kf[2*np+1][1],
                            ksub + sw);
                }
#pragma unroll
                for (int rt = 0; rt < 2; rt++)
#pragma unroll
                    for (int na = 0; na < 8; na++)
                        MMAF16(s[rt][na], qf[rt][ks], kf[na]);
            }

            // ---- online softmax per row-tile
#pragma unroll
            for (int rt = 0; rt < 2; rt++) {
                float mx0 = NEG_BIG, mx1 = NEG_BIG;
#pragma unroll
                for (int na = 0; na < 8; na++) {
                    mx0 = fmaxf(mx0, fmaxf(s[rt][na][0], s[rt][na][1]));
                    mx1 = fmaxf(mx1, fmaxf(s[rt][na][2], s[rt][na][3]));
                }
                mx0 = fmaxf(mx0, __shfl_xor_sync(0xffffffffu, mx0, 1));
                mx0 = fmaxf(mx0, __shfl_xor_sync(0xffffffffu, mx0, 2));
                mx1 = fmaxf(mx1, __shfl_xor_sync(0xffffffffu, mx1, 1));
                mx1 = fmaxf(mx1, __shfl_xor_sync(0xffffffffu, mx1, 2));
                const float mn0 = fmaxf(mr[rt][0], mx0);
                const float mn1 = fmaxf(mr[rt][1], mx1);
                const float al0 = __expf(mr[rt][0] - mn0);
                const float al1 = __expf(mr[rt][1] - mn1);
                mr[rt][0] = mn0; mr[rt][1] = mn1;
                float ls0 = 0.f, ls1 = 0.f;
#pragma unroll
                for (int na = 0; na < 8; na++) {
                    s[rt][na][0] = __expf(s[rt][na][0] - mn0);
                    s[rt][na][1] = __expf(s[rt][na][1] - mn0);
                    s[rt][na][2] = __expf(s[rt][na][2] - mn1);
                    s[rt][na][3] = __expf(s[rt][na][3] - mn1);
                    ls0 += s[rt][na][0] + s[rt][na][1];
                    ls1 += s[rt][na][2] + s[rt][na][3];
                }
                ls0 += __shfl_xor_sync(0xffffffffu, ls0, 1);
                ls0 += __shfl_xor_sync(0xffffffffu, ls0, 2);
                ls1 += __shfl_xor_sync(0xffffffffu, ls1, 1);
                ls1 += __shfl_xor_sync(0xffffffffu, ls1, 2);
                lr[rt][0] = lr[rt][0] * al0 + ls0;
                lr[rt][1] = lr[rt][1] * al1 + ls1;
#pragma unroll
                for (int na = 0; na < 8; na++) {
                    o[rt][na][0] *= al0; o[rt][na][1] *= al0;
                    o[rt][na][2] *= al1; o[rt][na][3] *= al1;
                }
            }

            // ---- P @ V: vf loaded once per kt, used by both row-tiles
#pragma unroll
            for (int kt = 0; kt < 4; kt++) {
                uint32_t vf[8][2];
#pragma unroll
                for (int dp = 0; dp < 4; dp++) {
                    const uint32_t byte = (uint32_t)((kt * 16 + (lane & 15)) * 128
                                                     + dp * 32 + (lane >> 4) * 16);
                    const uint32_t sw = SMEM_SWIZZLE_128B(byte);
                    LDSM_X4_T(vf[2*dp][0], vf[2*dp][1], vf[2*dp+1][0], vf[2*dp+1][1],
                              vsub + sw);
                }
#pragma unroll
                for (int rt = 0; rt < 2; rt++) {
                    uint32_t ph[4];
                    ph[0] = packh2(s[rt][2*kt][0],   s[rt][2*kt][1]);
                    ph[1] = packh2(s[rt][2*kt][2],   s[rt][2*kt][3]);
                    ph[2] = packh2(s[rt][2*kt+1][0], s[rt][2*kt+1][1]);
                    ph[3] = packh2(s[rt][2*kt+1][2], s[rt][2*kt+1][3]);
#pragma unroll
                    for (int na = 0; na < 8; na++)
                        MMAF16(o[rt][na], ph, vf[na]);
                }
            }
        }
        __syncthreads();
    }

    // ---- epilogue: normalize, write single fp16 plane
#pragma unroll
    for (int rt = 0; rt < 2; rt++) {
        const float inv0 = 1.f / lr[rt][0];
        const float inv1 = 1.f / lr[rt][1];
        const int row0 = q0 + wid * 32 + rt * 16 + (lane >> 2);
#pragma unroll
        for (int na = 0; na < 8; na++) {
            const int col = h * H_DIM + na * 8 + (lane & 3) * 2;
            const size_t i0 = (size_t)(b * SQ + row0) * E_DIM + col;
            const size_t i1 = (size_t)(b * SQ + row0 + 8) * E_DIM + col;
            *(uint32_t*)(Oh + i0) = packh2(o[rt][na][0] * inv0, o[rt][na][1] * inv0);
            *(uint32_t*)(Oh + i1) = packh2(o[rt][na][2] * inv1, o[rt][na][3] * inv1);
        }
    }
}

// ---------------------------------------------------------------------------
extern "C" void kernel_launch(void* const* d_in, const int* in_sizes, int n_in,
                              void* d_out, int out_size)
{
    const float* x1 = (const float*)d_in[0];
    const float* x2 = (const float*)d_in[1];
    const float* Wq = (const float*)d_in[2];
    const float* bq = (const float*)d_in[3];
    const float* Wk = (const float*)d_in[4];
    const float* bk = (const float*)d_in[5];
    const float* Wv = (const float*)d_in[6];
    const float* bv = (const float*)d_in[7];
    const float* Wo = (const float*)d_in[8];
    const float* bo = (const float*)d_in[9];
    float* out = (float*)d_out;

    uint16_t *x1h, *x2h;
    uint16_t *wqh, *wkh, *wvh, *woh;
    uint16_t *qh, *kh, *vh, *ah;
    cudaGetSymbolAddress((void**)&x1h, g_x1h);
    cudaGetSymbolAddress((void**)&x2h, g_x2h);
    cudaGetSymbolAddress((void**)&wqh, g_wqh);
    cudaGetSymbolAddress((void**)&wkh, g_wkh);
    cudaGetSymbolAddress((void**)&wvh, g_wvh);
    cudaGetSymbolAddress((void**)&woh, g_woh);
    cudaGetSymbolAddress((void**)&qh,  g_qh);
    cudaGetSymbolAddress((void**)&kh,  g_kh);
    cudaGetSymbolAddress((void**)&vh,  g_vh);
    cudaGetSymbolAddress((void**)&ah,  g_ah);

    cudaFuncSetAttribute(gemm_qkv, cudaFuncAttributeMaxDynamicSharedMemorySize, G_SMEM);
    cudaFuncSetAttribute(gemm_out, cudaFuncAttributeMaxDynamicSharedMemorySize, G_SMEM);
    cudaFuncSetAttribute(attn_mma, cudaFuncAttributeMaxDynamicSharedMemorySize, ATT_SMEM);

    // ---- stage 1: all plane conversions, one flat launch
    cvt_all<<<CVT_TOTAL / 256, 256>>>(
        x1, x2, Wq, Wk, Wv, Wo,
        x1h, x2h, wqh, wkh, wvh, woh);

    // ---- stage 2: fused Q/K/V projections, one launch (128-thread CTAs)
    gemm_qkv<<<dim3(8, MKV / 128, 3), G_THREADS, G_SMEM>>>(
        x1h, x2h, wqh, wkh, wvh,
        bq, bk, bv,
        qh, kh, vh);

    // ---- stage 3: attention (256 q rows per CTA)
    attn_mma<<<dim3(SQ / 256, N_HEADS, BATCH), 256, ATT_SMEM>>>(
        qh, kh, vh, ah);

    // ---- stage 4: output projection (fp32 out, 128-thread CTAs)
    gemm_out<<<dim3(8, MQ / 128), G_THREADS, G_SMEM>>>(ah, woh, bo, out);
}